// round 14
// baseline (speedup 1.0000x reference)
#include <cuda_runtime.h>
#include <cuda_fp16.h>
#include <cstdint>
#include <math.h>

// ---------------------------------------------------------------------------
// Problem constants
// ---------------------------------------------------------------------------
#define BATCH 4
#define LQ 1024
#define LK 2048
#define DIMM 1024
#define NH 16
#define DH 64
#define FF 4096

#define MQ (BATCH * LQ)   // 4096 query rows
#define MC (BATCH * LK)   // 8192 context rows

// ---------------------------------------------------------------------------
// Scratch (__device__ globals; allocation-free rule)
// ---------------------------------------------------------------------------
__device__ __half g_x16 [MQ * DIMM];
__device__ __half g_c16 [MC * DIMM];
__device__ __half g_Q16 [MQ * DIMM];        // pre-scaled by 1/8
__device__ __half g_KV16[MC * 2 * DIMM];    // fused: row stride 2048, K | V
__device__ __half g_O16 [MQ * DIMM];
__device__ __half g_X116[MQ * DIMM];        // X1 in fp16 (sole copy)
__device__ __half g_Hf16[MQ * FF];

__device__ __half g_WqT [DIMM * DIMM];      // [N,K]
__device__ __half g_WkvT[2 * DIMM * DIMM];  // rows 0..1023 = Wk^T, 1024..2047 = Wv^T
__device__ __half g_WoT [DIMM * DIMM];
__device__ __half g_W1T [FF * DIMM];
__device__ __half g_W2T [DIMM * FF];

// ---------------------------------------------------------------------------
// Helpers
// ---------------------------------------------------------------------------
__device__ __forceinline__ uint32_t smem_u32(const void* p) {
    uint32_t a;
    asm("{ .reg .u64 t; cvta.to.shared.u64 t, %1; cvt.u32.u64 %0, t; }"
        : "=r"(a) : "l"(p));
    return a;
}

__device__ __forceinline__ void ldsm_x4(uint32_t* r, uint32_t addr) {
    asm volatile("ldmatrix.sync.aligned.m8n8.x4.shared.b16 {%0,%1,%2,%3}, [%4];"
                 : "=r"(r[0]), "=r"(r[1]), "=r"(r[2]), "=r"(r[3]) : "r"(addr));
}
__device__ __forceinline__ void ldsm_x4_t(uint32_t* r, uint32_t addr) {
    asm volatile("ldmatrix.sync.aligned.m8n8.x4.trans.shared.b16 {%0,%1,%2,%3}, [%4];"
                 : "=r"(r[0]), "=r"(r[1]), "=r"(r[2]), "=r"(r[3]) : "r"(addr));
}
__device__ __forceinline__ void ldsm_x2(uint32_t* r, uint32_t addr) {
    asm volatile("ldmatrix.sync.aligned.m8n8.x2.shared.b16 {%0,%1}, [%2];"
                 : "=r"(r[0]), "=r"(r[1]) : "r"(addr));
}

// D += A(16x16,row) * B(16x8,col), fp16 in, fp32 accum
__device__ __forceinline__ void mma16816(float* c, const uint32_t* a,
                                         uint32_t b0, uint32_t b1) {
    asm volatile(
        "mma.sync.aligned.m16n8k16.row.col.f32.f16.f16.f32 "
        "{%0,%1,%2,%3}, {%4,%5,%6,%7}, {%8,%9}, {%0,%1,%2,%3};"
        : "+f"(c[0]), "+f"(c[1]), "+f"(c[2]), "+f"(c[3])
        : "r"(a[0]), "r"(a[1]), "r"(a[2]), "r"(a[3]), "r"(b0), "r"(b1));
}

#define CP_ASYNC16(dst, src) \
    asm volatile("cp.async.cg.shared.global [%0], [%1], 16;" :: "r"(dst), "l"(src))
#define CP_COMMIT() asm volatile("cp.async.commit_group;" ::: "memory")
#define CP_WAIT0()  asm volatile("cp.async.wait_group 0;" ::: "memory")

__device__ __forceinline__ float gelu_exact(float x) {
    return 0.5f * x * (1.0f + erff(x * 0.70710678118654752f));
}

// ---------------------------------------------------------------------------
// Preproc: cvt x16 / cvt c16 / all six weight transposes, in ONE launch
// ---------------------------------------------------------------------------
__device__ __forceinline__ void tr_tile(const float* __restrict__ W,
                                        __half* __restrict__ WT,
                                        int K, int N, int bx, int by,
                                        __half (*t)[68])
{
    const int n0 = bx * 64, k0 = by * 64;
    const int tid = threadIdx.x;
    const int lr = tid >> 4;
    const int lc = (tid & 15) * 4;
#pragma unroll
    for (int i = 0; i < 4; i++) {
        const int k = lr + i * 16;
        float4 v = *(const float4*)&W[(size_t)(k0 + k) * N + n0 + lc];
        __half2* dst = (__half2*)&t[k][lc];
        dst[0] = __floats2half2_rn(v.x, v.y);
        dst[1] = __floats2half2_rn(v.z, v.w);
    }
    __syncthreads();
    const int sn  = tid & 63;
    const int sk0 = (tid >> 6) * 16;
#pragma unroll
    for (int j2 = 0; j2 < 2; j2++) {
        __half buf[8];
#pragma unroll
        for (int j = 0; j < 8; j++) buf[j] = t[sk0 + j2 * 8 + j][sn];
        *(uint4*)&WT[(size_t)(n0 + sn) * K + k0 + sk0 + j2 * 8] = *(uint4*)buf;
    }
}

__device__ __forceinline__ void cvt_chunk(const float4* __restrict__ src,
                                          __half2* __restrict__ dst, int i)
{
    float4 v = src[i];
    dst[2 * i]     = __floats2half2_rn(v.x, v.y);
    dst[2 * i + 1] = __floats2half2_rn(v.z, v.w);
}

// blocks: [0,4096) cvt x | [4096,12288) cvt c | [12288,15360) transposes
__global__ __launch_bounds__(256) void preproc_all(
    const float* __restrict__ x,  const float* __restrict__ ctx,
    const float* __restrict__ Wq, const float* __restrict__ Wk,
    const float* __restrict__ Wv, const float* __restrict__ Wo,
    const float* __restrict__ W1, const float* __restrict__ W2,
    __half* __restrict__ x16,  __half* __restrict__ c16,
    __half* __restrict__ WqT,  __half* __restrict__ WkvT,
    __half* __restrict__ WoT,  __half* __restrict__ W1T, __half* __restrict__ W2T)
{
    __shared__ __half t[64][68];
    const int b = blockIdx.x;
    if (b < 4096) {
        cvt_chunk((const float4*)x, (__half2*)x16, b * 256 + threadIdx.x);
    } else if (b < 12288) {
        cvt_chunk((const float4*)ctx, (__half2*)c16, (b - 4096) * 256 + threadIdx.x);
    } else {
        const int tb = b - 12288;
        if (tb < 256)       tr_tile(Wq, WqT,                DIMM, DIMM, tb % 16,          tb / 16,          t);
        else if (tb < 512)  tr_tile(Wk, WkvT,               DIMM, DIMM, (tb - 256) % 16,  (tb - 256) / 16,  t);
        else if (tb < 768)  tr_tile(Wv, WkvT + DIMM * DIMM, DIMM, DIMM, (tb - 512) % 16,  (tb - 512) / 16,  t);
        else if (tb < 1024) tr_tile(Wo, WoT,                DIMM, DIMM, (tb - 768) % 16,  (tb - 768) / 16,  t);
        else if (tb < 2048) tr_tile(W1, W1T,                DIMM, FF,   (tb - 1024) % 64, (tb - 1024) / 64, t);
        else                tr_tile(W2, W2T,                FF,   DIMM, (tb - 2048) % 16, (tb - 2048) / 16, t);
    }
}

// ---------------------------------------------------------------------------
// HMMA fp16 GEMM body: C = A[M,K] @ B^T, B = WT[N,K].
// CTA 128x128, BK=64, 256 threads (8 warps, warp tile 64x32).
// 2-STAGE cp.async (prefetch depth 1) -> 73.7KB smem -> 2 CTAs/SM
// (256-CTA GEMMs become single-wave).
// EPI: 1 bias + res16 -> fp16 out ; 2 gelu(acc+bias) -> fp16 ;
//      3 bias + res16 -> fp32 out ; 4 fp16 out, *sc
// ---------------------------------------------------------------------------
#define PADK 72
#define STAGES 2
#define STAGE_HALVES (128 * PADK)
#define GSMEM_BYTES (STAGES * 2 * STAGE_HALVES * 2)

template <int EPI>
__device__ __forceinline__ void gemm_body(
    __half* smh,
    const __half* __restrict__ A, const __half* __restrict__ B,
    const float* __restrict__ bias, const __half* __restrict__ res16,
    float* __restrict__ C32, __half* __restrict__ C16,
    int M, int N, int K, float sc, int bx, int by)
{
    const uint32_t asBase = smem_u32(smh);
    const uint32_t bsBase = asBase + STAGES * STAGE_HALVES * 2;

    const int tid  = threadIdx.x;
    const int warp = tid >> 5;
    const int lane = tid & 31;
    const int wm0 = (warp & 1) * 64;
    const int wn0 = (warp >> 1) * 32;

    const int rowBase = by * 128;
    const int colBase = bx * 128;
    const __half* Atile = A + (size_t)rowBase * K;
    const __half* Btile = B + (size_t)colBase * K;

    const int ldRow = tid >> 3;
    const int ldSeg = (tid & 7) * 8;

    const int aRow = (lane & 15);
    const int aCol = (lane >> 4) * 8;
    const int bRow = (lane & 7);
    const int bCol = ((lane >> 3) & 1) * 8;

    float c[4][4][4];
#pragma unroll
    for (int mi = 0; mi < 4; mi++)
#pragma unroll
        for (int ni = 0; ni < 4; ni++)
#pragma unroll
            for (int j = 0; j < 4; j++) c[mi][ni][j] = 0.0f;

    const int numK = K >> 6;

    auto issue_stage = [&](int stage, int kt) {
        const int k0 = kt * 64;
        const uint32_t ad = asBase + (uint32_t)((stage * 128 + ldRow) * PADK + ldSeg) * 2;
        const uint32_t bd = bsBase + (uint32_t)((stage * 128 + ldRow) * PADK + ldSeg) * 2;
        const __half* as = Atile + (size_t)ldRow * K + k0 + ldSeg;
        const __half* bs = Btile + (size_t)ldRow * K + k0 + ldSeg;
#pragma unroll
        for (int i = 0; i < 4; i++) {
            CP_ASYNC16(ad + (uint32_t)(i * 32 * PADK) * 2, as + (size_t)(i * 32) * K);
            CP_ASYNC16(bd + (uint32_t)(i * 32 * PADK) * 2, bs + (size_t)(i * 32) * K);
        }
    };

    issue_stage(0, 0); CP_COMMIT();

    for (int kt = 0; kt < numK; kt++) {
        const int p = kt & 1;
        CP_WAIT0();            // tile kt landed
        __syncthreads();       // all warps done with buf p^1
        if (kt + 1 < numK) { issue_stage(p ^ 1, kt + 1); CP_COMMIT(); }

        const uint32_t aBuf = asBase + (uint32_t)(p * STAGE_HALVES) * 2;
        const uint32_t bBuf = bsBase + (uint32_t)(p * STAGE_HALVES) * 2;
#pragma unroll
        for (int ks = 0; ks < 4; ks++) {
            uint32_t af[4][4], bf[4][2];
#pragma unroll
            for (int mi = 0; mi < 4; mi++)
                ldsm_x4(af[mi], aBuf + (uint32_t)((wm0 + mi * 16 + aRow) * PADK + ks * 16 + aCol) * 2);
#pragma unroll
            for (int ni = 0; ni < 4; ni++)
                ldsm_x2(bf[ni], bBuf + (uint32_t)((wn0 + ni * 8 + bRow) * PADK + ks * 16 + bCol) * 2);
#pragma unroll
            for (int mi = 0; mi < 4; mi++)
#pragma unroll
                for (int ni = 0; ni < 4; ni++)
                    mma16816(c[mi][ni], af[mi], bf[ni][0], bf[ni][1]);
        }
    }

    const int g  = lane >> 2;
    const int th = (lane & 3) * 2;
#pragma unroll
    for (int mi = 0; mi < 4; mi++) {
#pragma unroll
        for (int half = 0; half < 2; half++) {
            const int row = rowBase + wm0 + mi * 16 + g + half * 8;
#pragma unroll
            for (int ni = 0; ni < 4; ni++) {
                const int col = colBase + wn0 + ni * 8 + th;
                float v0 = c[mi][ni][half * 2 + 0];
                float v1 = c[mi][ni][half * 2 + 1];
                if (EPI == 1 || EPI == 3) {
                    const __half2 r16 = *(const __half2*)&res16[(size_t)row * N + col];
                    const float2 rf = __half22float2(r16);
                    v0 += bias[col]     + rf.x;
                    v1 += bias[col + 1] + rf.y;
                } else if (EPI == 2) {
                    v0 = gelu_exact(v0 + bias[col]);
                    v1 = gelu_exact(v1 + bias[col + 1]);
                } else if (EPI == 4) {
                    v0 *= sc; v1 *= sc;
                }
                if (EPI == 3)
                    *(float2*)&C32[(size_t)row * N + col] = make_float2(v0, v1);
                else
                    *(__half2*)&C16[(size_t)row * N + col] = __floats2half2_rn(v0, v1);
            }
        }
    }
}

template <int EPI>
__global__ __launch_bounds__(256) void tc_gemm(
    const __half* __restrict__ A, const __half* __restrict__ B,
    const float* __restrict__ bias, const __half* __restrict__ res16,
    float* __restrict__ C32, __half* __restrict__ C16,
    int M, int N, int K, float sc)
{
    extern __shared__ __half smh[];
    gemm_body<EPI>(smh, A, B, bias, res16, C32, C16, M, N, K, sc,
                   blockIdx.x, blockIdx.y);
}

// Fused Q + KV projection launch: blocks [0,1024) = KV, [1024,1280) = Q.
__global__ __launch_bounds__(256) void qkv_gemm(
    const __half* __restrict__ x16, const __half* __restrict__ c16,
    const __half* __restrict__ WqT, const __half* __restrict__ WkvT,
    __half* __restrict__ Q16, __half* __restrict__ KV16)
{
    extern __shared__ __half smh[];
    const int b = blockIdx.x;
    if (b < 1024) {
        gemm_body<4>(smh, c16, WkvT, nullptr, nullptr, nullptr, KV16,
                     MC, 2 * DIMM, DIMM, 1.0f, b & 15, b >> 4);
    } else {
        const int q = b - 1024;
        gemm_body<4>(smh, x16, WqT, nullptr, nullptr, nullptr, Q16,
                     MQ, DIMM, DIMM, 0.125f, q & 7, q >> 3);
    }
}

// ---------------------------------------------------------------------------
// MMA flash attention: 128 q-rows/CTA, cp.async K/V double-buffer,
// Q fragments hoisted to registers (loop-invariant).
// ---------------------------------------------------------------------------
#define PADA 72
#define QS_H   (128 * PADA)
#define KV_H   (64 * PADA)
#define ATT_SMEM ((QS_H + 4 * KV_H) * 2)

__global__ __launch_bounds__(256) void attn_mma(
    const __half* __restrict__ Q16, const __half* __restrict__ KV16,
    __half* __restrict__ O16)
{
    extern __shared__ __half sm[];
    const uint32_t qsB = smem_u32(sm);
    const uint32_t ksB = qsB + QS_H * 2;
    const uint32_t vsB = ksB + 2 * KV_H * 2;

    const int b = blockIdx.z;
    const int h = blockIdx.y;
    const int q0 = blockIdx.x * 128;
    const int tid = threadIdx.x;
    const int warp = tid >> 5;
    const int lane = tid & 31;
    const int g  = lane >> 2;
    const int th = (lane & 3) * 2;

    for (int i = tid; i < 1024; i += 256) {
        const int row = i >> 3, seg = (i & 7) * 8;
        *(uint4*)(sm + row * PADA + seg) =
            *(const uint4*)&Q16[(size_t)(b * LQ + q0 + row) * DIMM + h * DH + seg];
    }

    const int lrow = tid >> 3;
    const int lseg = (tid & 7) * 8;

    auto issue_kv = [&](int p, int k0) {
        const size_t gb = ((size_t)(b * LK + k0 + lrow)) * (2 * DIMM) + h * DH + lseg;
        const uint32_t kd = ksB + (uint32_t)(p * KV_H + lrow * PADA + lseg) * 2;
        const uint32_t vd = vsB + (uint32_t)(p * KV_H + lrow * PADA + lseg) * 2;
        CP_ASYNC16(kd, KV16 + gb);
        CP_ASYNC16(kd + 32 * PADA * 2, KV16 + gb + (size_t)32 * (2 * DIMM));
        CP_ASYNC16(vd, KV16 + gb + DIMM);
        CP_ASYNC16(vd + 32 * PADA * 2, KV16 + gb + DIMM + (size_t)32 * (2 * DIMM));
    };

    issue_kv(0, 0); CP_COMMIT();

    const int aRow = lane & 15;
    const int aCol = (lane >> 4) * 8;
    const int vq = lane >> 3;
    const int vi = lane & 7;
    const int vTokOff = (vq & 1) * 8 + vi;
    const int vDimOff = (vq >> 1) * 8;

    // Hoist Q fragments (loop-invariant) into registers
    __syncthreads();
    uint32_t aq[4][4];
#pragma unroll
    for (int kc = 0; kc < 4; kc++)
        ldsm_x4(aq[kc], qsB + (uint32_t)((warp * 16 + aRow) * PADA + kc * 16 + aCol) * 2);

    float m0 = -INFINITY, m1 = -INFINITY, l0 = 0.f, l1 = 0.f;
    float o[8][4];
#pragma unroll
    for (int j = 0; j < 8; j++)
#pragma unroll
        for (int q = 0; q < 4; q++) o[j][q] = 0.f;

    for (int kt = 0; kt < LK / 64; kt++) {
        const int p = kt & 1;
        CP_WAIT0();
        __syncthreads();
        if (kt + 1 < LK / 64) { issue_kv(p ^ 1, (kt + 1) * 64); CP_COMMIT(); }

        const uint32_t kBuf = ksB + (uint32_t)(p * KV_H) * 2;
        const uint32_t vBuf = vsB + (uint32_t)(p * KV_H) * 2;

        float s[8][4];
#pragma unroll
        for (int j = 0; j < 8; j++)
#pragma unroll
            for (int q = 0; q < 4; q++) s[j][q] = 0.f;

#pragma unroll
        for (int kc = 0; kc < 4; kc++) {
#pragma unroll
            for (int np = 0; np < 4; np++) {
                uint32_t bf[4];
                ldsm_x4(bf, kBuf + (uint32_t)((np * 16 + aRow) * PADA + kc * 16 + aCol) * 2);
                mma16816(s[np * 2],     aq[kc], bf[0], bf[2]);
                mma16816(s[np * 2 + 1], aq[kc], bf[1], bf[3]);
            }
        }

        float rm0 = s[0][0], rm1 = s[0][2];
#pragma unroll
        for (int j = 0; j < 8; j++) {
            rm0 = fmaxf(rm0, fmaxf(s[j][0], s[j][1]));
            rm1 = fmaxf(rm1, fmaxf(s[j][2], s[j][3]));
        }
        rm0 = fmaxf(rm0, __shfl_xor_sync(0xffffffffu, rm0, 1));
        rm0 = fmaxf(rm0, __shfl_xor_sync(0xffffffffu, rm0, 2));
        rm1 = fmaxf(rm1, __shfl_xor_sync(0xffffffffu, rm1, 1));
        rm1 = fmaxf(rm1, __shfl_xor_sync(0xffffffffu, rm1, 2));

        const float m0n = fmaxf(m0, rm0);
        const float m1n = fmaxf(m1, rm1);
        const float sc0 = __expf(m0 - m0n);
        const float sc1 = __expf(m1 - m1n);
        m0 = m0n; m1 = m1n;

        float ps0 = 0.f, ps1 = 0.f;
#pragma unroll
        for (int j = 0; j < 8; j++) {
            s[j][0] = __expf(s[j][0] - m0n);
            s[j][1] = __expf(s[j][1] - m0n);
            s[j][2] = __expf(s[j][2] - m1n);
            s[j][3] = __expf(s[j][3] - m1n);
            ps0 += s[j][0] + s[j][1];
            ps1 += s[j][2] + s[j][3];
        }
        l0 = l0 * sc0 + ps0;
        l1 = l1 * sc1 + ps1;
#pragma unroll
        for (int j = 0; j < 8; j++) {
            o[j][0] *= sc0; o[j][1] *= sc0;
            o[j][2] *= sc1; o[j][3] *= sc1;
        }

        uint32_t ap[4][4];
#pragma unroll
        for (int kc = 0; kc < 4; kc++) {
            __half2 h0 = __floats2half2_rn(s[2 * kc][0],     s[2 * kc][1]);
            __half2 h1 = __floats2half2_rn(s[2 * kc][2],     s[2 * kc][3]);
            __half2 h2 = __floats2half2_rn(s[2 * kc + 1][0], s[2 * kc + 1][1]);
            __half2 h3 = __floats2half2_rn(s[2 * kc + 1][2], s[2 * kc + 1][3]);
            ap[kc][0] = *(uint32_t*)&h0;
            ap[kc][1] = *(uint32_t*)&h1;
            ap[kc][2] = *(uint32_t*)&h2;
            ap[kc][3] = *(uint32_t*)&h3;
        }

#pragma unroll
        for (int kc = 0; kc < 4; kc++) {
#pragma unroll
            for (int nt2 = 0; nt2 < 4; nt2++) {
                uint32_t bv[4];
                const int token = kc * 16 + vTokOff;
                const int dim   = nt2 * 16 + vDimOff;
                ldsm_x4_t(bv, vBuf + (uint32_t)(token * PADA + dim) * 2);
                mma16816(o[nt2 * 2],     ap[kc], bv[0], bv[1]);
                mma16816(o[nt2 * 2 + 1], ap[kc], bv[2], bv[3]);
            }
        }
        __syncthreads();
    }

    l0 += __shfl_xor_sync(0xffffffffu, l0, 1);
    l0 += __shfl_xor_sync(0xffffffffu, l0, 2);
    l1 += __shfl_xor_sync(0xffffffffu, l1, 1);
    l1 += __shfl_xor_sync(0xffffffffu, l1, 2);
    const float inv0 = 1.0f / l0;
    const float inv1 = 1.0f / l1;

    const int row0 = b * LQ + q0 + warp * 16 + g;
#pragma unroll
    for (int j = 0; j < 8; j++) {
        const int col = h * DH + j * 8 + th;
        *(__half2*)&O16[(size_t)row0 * DIMM + col] =
            __floats2half2_rn(o[j][0] * inv0, o[j][1] * inv0);
        *(__half2*)&O16[(size_t)(row0 + 8) * DIMM + col] =
            __floats2half2_rn(o[j][2] * inv1, o[j][3] * inv1);
    }
}

// ---------------------------------------------------------------------------
// Launch sequence
// ---------------------------------------------------------------------------
extern "C" void kernel_launch(void* const* d_in, const int* in_sizes, int n_in,
                              void* d_out, int out_size)
{
    const float* x   = (const float*)d_in[0];
    const float* ctx = (const float*)d_in[1];
    const float* Wq  = (const float*)d_in[2];
    const float* Wk  = (const float*)d_in[3];
    const float* Wv  = (const float*)d_in[4];
    const float* Wo  = (const float*)d_in[5];
    const float* bo  = (const float*)d_in[6];
    const float* W1  = (const float*)d_in[7];
    const float* b1  = (const float*)d_in[8];
    const float* W2  = (const float*)d_in[9];
    const float* b2  = (const float*)d_in[10];
    float* out = (float*)d_out;

    __half *x16, *c16, *Q16, *KV16, *O16, *X116, *Hf16;
    __half *WqT, *WkvT, *WoT, *W1T, *W2T;
    cudaGetSymbolAddress((void**)&x16,  g_x16);
    cudaGetSymbolAddress((void**)&c16,  g_c16);
    cudaGetSymbolAddress((void**)&Q16,  g_Q16);
    cudaGetSymbolAddress((void**)&KV16, g_KV16);
    cudaGetSymbolAddress((void**)&O16,  g_O16);
    cudaGetSymbolAddress((void**)&X116, g_X116);
    cudaGetSymbolAddress((void**)&Hf16, g_Hf16);
    cudaGetSymbolAddress((void**)&WqT,  g_WqT);
    cudaGetSymbolAddress((void**)&WkvT, g_WkvT);
    cudaGetSymbolAddress((void**)&WoT,  g_WoT);
    cudaGetSymbolAddress((void**)&W1T,  g_W1T);
    cudaGetSymbolAddress((void**)&W2T,  g_W2T);

    cudaFuncSetAttribute(qkv_gemm,   cudaFuncAttributeMaxDynamicSharedMemorySize, GSMEM_BYTES);
    cudaFuncSetAttribute(tc_gemm<1>, cudaFuncAttributeMaxDynamicSharedMemorySize, GSMEM_BYTES);
    cudaFuncSetAttribute(tc_gemm<2>, cudaFuncAttributeMaxDynamicSharedMemorySize, GSMEM_BYTES);
    cudaFuncSetAttribute(tc_gemm<3>, cudaFuncAttributeMaxDynamicSharedMemorySize, GSMEM_BYTES);
    cudaFuncSetAttribute(attn_mma,   cudaFuncAttributeMaxDynamicSharedMemorySize, ATT_SMEM);

    // Preproc: conversions + all weight transposes in one launch
    preproc_all<<<15360, 256>>>(x, ctx, Wq, Wk, Wv, Wo, W1, W2,
                                x16, c16, WqT, WkvT, WoT, W1T, W2T);

    // Fused Q + KV projection (Q pre-scaled by 1/8)
    qkv_gemm<<<1280, 256, GSMEM_BYTES>>>(x16, c16, WqT, WkvT, Q16, KV16);

    // MMA flash attention -> O16
    attn_mma<<<dim3(LQ / 128, NH, BATCH), 256, ATT_SMEM>>>(Q16, KV16, O16);

    // X116 = fp16( O@Wo + bo + x16 )   (residual from fp16)
    tc_gemm<1><<<dim3(DIMM / 128, MQ / 128), 256, GSMEM_BYTES>>>(O16, WoT, bo, x16, nullptr, X116, MQ, DIMM, DIMM, 1.0f);

    // Hf = gelu(X1@W1 + b1)
    tc_gemm<2><<<dim3(FF / 128, MQ / 128), 256, GSMEM_BYTES>>>(X116, W1T, b1, nullptr, nullptr, Hf16, MQ, FF, DIMM, 1.0f);

    // out = Hf@W2 + b2 + X116   (residual from fp16)
    tc_gemm<3><<<dim3(DIMM / 128, MQ / 128), 256, GSMEM_BYTES>>>(Hf16, W2T, b2, X116, out, nullptr, MQ, DIMM, FF, 1.0f);
}

// round 15
// speedup vs baseline: 1.0147x; 1.0147x over previous
#include <cuda_runtime.h>
#include <cuda_fp16.h>
#include <cstdint>
#include <math.h>

// ---------------------------------------------------------------------------
// Problem constants
// ---------------------------------------------------------------------------
#define BATCH 4
#define LQ 1024
#define LK 2048
#define DIMM 1024
#define NH 16
#define DH 64
#define FF 4096

#define MQ (BATCH * LQ)   // 4096 query rows
#define MC (BATCH * LK)   // 8192 context rows

// ---------------------------------------------------------------------------
// Scratch (__device__ globals; allocation-free rule)
// ---------------------------------------------------------------------------
__device__ __half g_x16 [MQ * DIMM];
__device__ __half g_c16 [MC * DIMM];
__device__ __half g_Q16 [MQ * DIMM];        // pre-scaled by 1/8
__device__ __half g_KV16[MC * 2 * DIMM];    // fused: row stride 2048, K | V
__device__ __half g_O16 [MQ * DIMM];
__device__ __half g_X116[MQ * DIMM];        // X1 in fp16 (sole copy)
__device__ __half g_Hf16[MQ * FF];

__device__ __half g_WqT [DIMM * DIMM];      // [N,K]
__device__ __half g_WkvT[2 * DIMM * DIMM];  // rows 0..1023 = Wk^T, 1024..2047 = Wv^T
__device__ __half g_WoT [DIMM * DIMM];
__device__ __half g_W1T [FF * DIMM];
__device__ __half g_W2T [DIMM * FF];

// ---------------------------------------------------------------------------
// Helpers
// ---------------------------------------------------------------------------
__device__ __forceinline__ uint32_t smem_u32(const void* p) {
    uint32_t a;
    asm("{ .reg .u64 t; cvta.to.shared.u64 t, %1; cvt.u32.u64 %0, t; }"
        : "=r"(a) : "l"(p));
    return a;
}

__device__ __forceinline__ void ldsm_x4(uint32_t* r, uint32_t addr) {
    asm volatile("ldmatrix.sync.aligned.m8n8.x4.shared.b16 {%0,%1,%2,%3}, [%4];"
                 : "=r"(r[0]), "=r"(r[1]), "=r"(r[2]), "=r"(r[3]) : "r"(addr));
}
__device__ __forceinline__ void ldsm_x4_t(uint32_t* r, uint32_t addr) {
    asm volatile("ldmatrix.sync.aligned.m8n8.x4.trans.shared.b16 {%0,%1,%2,%3}, [%4];"
                 : "=r"(r[0]), "=r"(r[1]), "=r"(r[2]), "=r"(r[3]) : "r"(addr));
}
__device__ __forceinline__ void ldsm_x2(uint32_t* r, uint32_t addr) {
    asm volatile("ldmatrix.sync.aligned.m8n8.x2.shared.b16 {%0,%1}, [%2];"
                 : "=r"(r[0]), "=r"(r[1]) : "r"(addr));
}

// D += A(16x16,row) * B(16x8,col), fp16 in, fp32 accum
__device__ __forceinline__ void mma16816(float* c, const uint32_t* a,
                                         uint32_t b0, uint32_t b1) {
    asm volatile(
        "mma.sync.aligned.m16n8k16.row.col.f32.f16.f16.f32 "
        "{%0,%1,%2,%3}, {%4,%5,%6,%7}, {%8,%9}, {%0,%1,%2,%3};"
        : "+f"(c[0]), "+f"(c[1]), "+f"(c[2]), "+f"(c[3])
        : "r"(a[0]), "r"(a[1]), "r"(a[2]), "r"(a[3]), "r"(b0), "r"(b1));
}

#define CP_ASYNC16(dst, src) \
    asm volatile("cp.async.cg.shared.global [%0], [%1], 16;" :: "r"(dst), "l"(src))
#define CP_COMMIT() asm volatile("cp.async.commit_group;" ::: "memory")
#define CP_WAIT1()  asm volatile("cp.async.wait_group 1;" ::: "memory")
#define CP_WAIT0()  asm volatile("cp.async.wait_group 0;" ::: "memory")

__device__ __forceinline__ float gelu_exact(float x) {
    return 0.5f * x * (1.0f + erff(x * 0.70710678118654752f));
}

// ---------------------------------------------------------------------------
// Preproc: cvt x16 / cvt c16 / all six weight transposes, in ONE launch
// ---------------------------------------------------------------------------
__device__ __forceinline__ void tr_tile(const float* __restrict__ W,
                                        __half* __restrict__ WT,
                                        int K, int N, int bx, int by,
                                        __half (*t)[68])
{
    const int n0 = bx * 64, k0 = by * 64;
    const int tid = threadIdx.x;
    const int lr = tid >> 4;
    const int lc = (tid & 15) * 4;
#pragma unroll
    for (int i = 0; i < 4; i++) {
        const int k = lr + i * 16;
        float4 v = *(const float4*)&W[(size_t)(k0 + k) * N + n0 + lc];
        __half2* dst = (__half2*)&t[k][lc];
        dst[0] = __floats2half2_rn(v.x, v.y);
        dst[1] = __floats2half2_rn(v.z, v.w);
    }
    __syncthreads();
    const int sn  = tid & 63;
    const int sk0 = (tid >> 6) * 16;
#pragma unroll
    for (int j2 = 0; j2 < 2; j2++) {
        __half buf[8];
#pragma unroll
        for (int j = 0; j < 8; j++) buf[j] = t[sk0 + j2 * 8 + j][sn];
        *(uint4*)&WT[(size_t)(n0 + sn) * K + k0 + sk0 + j2 * 8] = *(uint4*)buf;
    }
}

__device__ __forceinline__ void cvt_chunk(const float4* __restrict__ src,
                                          __half2* __restrict__ dst, int i)
{
    float4 v = src[i];
    dst[2 * i]     = __floats2half2_rn(v.x, v.y);
    dst[2 * i + 1] = __floats2half2_rn(v.z, v.w);
}

// blocks: [0,4096) cvt x | [4096,12288) cvt c | [12288,15360) transposes
__global__ __launch_bounds__(256) void preproc_all(
    const float* __restrict__ x,  const float* __restrict__ ctx,
    const float* __restrict__ Wq, const float* __restrict__ Wk,
    const float* __restrict__ Wv, const float* __restrict__ Wo,
    const float* __restrict__ W1, const float* __restrict__ W2,
    __half* __restrict__ x16,  __half* __restrict__ c16,
    __half* __restrict__ WqT,  __half* __restrict__ WkvT,
    __half* __restrict__ WoT,  __half* __restrict__ W1T, __half* __restrict__ W2T)
{
    __shared__ __half t[64][68];
    const int b = blockIdx.x;
    if (b < 4096) {
        cvt_chunk((const float4*)x, (__half2*)x16, b * 256 + threadIdx.x);
    } else if (b < 12288) {
        cvt_chunk((const float4*)ctx, (__half2*)c16, (b - 4096) * 256 + threadIdx.x);
    } else {
        const int tb = b - 12288;
        if (tb < 256)       tr_tile(Wq, WqT,                DIMM, DIMM, tb % 16,          tb / 16,          t);
        else if (tb < 512)  tr_tile(Wk, WkvT,               DIMM, DIMM, (tb - 256) % 16,  (tb - 256) / 16,  t);
        else if (tb < 768)  tr_tile(Wv, WkvT + DIMM * DIMM, DIMM, DIMM, (tb - 512) % 16,  (tb - 512) / 16,  t);
        else if (tb < 1024) tr_tile(Wo, WoT,                DIMM, DIMM, (tb - 768) % 16,  (tb - 768) / 16,  t);
        else if (tb < 2048) tr_tile(W1, W1T,                DIMM, FF,   (tb - 1024) % 64, (tb - 1024) / 64, t);
        else                tr_tile(W2, W2T,                FF,   DIMM, (tb - 2048) % 16, (tb - 2048) / 16, t);
    }
}

// ---------------------------------------------------------------------------
// HMMA fp16 GEMM body (R13/R11 champion mainloop): 3-stage cp.async.
// C = A[M,K] @ B^T, B = WT[N,K]. CTA 128x128, BK=64, 256 threads.
// EPI: 1 bias + res16 -> fp16 out ; 2 gelu(acc+bias) -> fp16 ;
//      3 bias + res16 -> fp32 out ; 4 fp16 out, *sc
// ---------------------------------------------------------------------------
#define PADK 72
#define STAGES 3
#define STAGE_HALVES (128 * PADK)
#define GSMEM_BYTES (STAGES * 2 * STAGE_HALVES * 2)

template <int EPI>
__device__ __forceinline__ void gemm_body(
    __half* smh,
    const __half* __restrict__ A, const __half* __restrict__ B,
    const float* __restrict__ bias, const __half* __restrict__ res16,
    float* __restrict__ C32, __half* __restrict__ C16,
    int M, int N, int K, float sc, int bx, int by)
{
    const uint32_t asBase = smem_u32(smh);
    const uint32_t bsBase = asBase + STAGES * STAGE_HALVES * 2;

    const int tid  = threadIdx.x;
    const int warp = tid >> 5;
    const int lane = tid & 31;
    const int wm0 = (warp & 1) * 64;
    const int wn0 = (warp >> 1) * 32;

    const int rowBase = by * 128;
    const int colBase = bx * 128;
    const __half* Atile = A + (size_t)rowBase * K;
    const __half* Btile = B + (size_t)colBase * K;

    const int ldRow = tid >> 3;
    const int ldSeg = (tid & 7) * 8;

    const int aRow = (lane & 15);
    const int aCol = (lane >> 4) * 8;
    const int bRow = (lane & 7);
    const int bCol = ((lane >> 3) & 1) * 8;

    float c[4][4][4];
#pragma unroll
    for (int mi = 0; mi < 4; mi++)
#pragma unroll
        for (int ni = 0; ni < 4; ni++)
#pragma unroll
            for (int j = 0; j < 4; j++) c[mi][ni][j] = 0.0f;

    const int numK = K >> 6;

    auto issue_stage = [&](int stage, int kt) {
        const int k0 = kt * 64;
        const uint32_t ad = asBase + (uint32_t)((stage * 128 + ldRow) * PADK + ldSeg) * 2;
        const uint32_t bd = bsBase + (uint32_t)((stage * 128 + ldRow) * PADK + ldSeg) * 2;
        const __half* as = Atile + (size_t)ldRow * K + k0 + ldSeg;
        const __half* bs = Btile + (size_t)ldRow * K + k0 + ldSeg;
#pragma unroll
        for (int i = 0; i < 4; i++) {
            CP_ASYNC16(ad + (uint32_t)(i * 32 * PADK) * 2, as + (size_t)(i * 32) * K);
            CP_ASYNC16(bd + (uint32_t)(i * 32 * PADK) * 2, bs + (size_t)(i * 32) * K);
        }
    };

    issue_stage(0, 0); CP_COMMIT();
    issue_stage(1, 1); CP_COMMIT();

    for (int kt = 0; kt < numK; kt++) {
        CP_WAIT1();
        __syncthreads();

        const int st = kt % STAGES;
        const uint32_t aBuf = asBase + (uint32_t)(st * STAGE_HALVES) * 2;
        const uint32_t bBuf = bsBase + (uint32_t)(st * STAGE_HALVES) * 2;
#pragma unroll
        for (int ks = 0; ks < 4; ks++) {
            uint32_t af[4][4], bf[4][2];
#pragma unroll
            for (int mi = 0; mi < 4; mi++)
                ldsm_x4(af[mi], aBuf + (uint32_t)((wm0 + mi * 16 + aRow) * PADK + ks * 16 + aCol) * 2);
#pragma unroll
            for (int ni = 0; ni < 4; ni++)
                ldsm_x2(bf[ni], bBuf + (uint32_t)((wn0 + ni * 8 + bRow) * PADK + ks * 16 + bCol) * 2);
#pragma unroll
            for (int mi = 0; mi < 4; mi++)
#pragma unroll
                for (int ni = 0; ni < 4; ni++)
                    mma16816(c[mi][ni], af[mi], bf[ni][0], bf[ni][1]);
        }

        const int ktn = kt + STAGES - 1;
        if (ktn < numK) issue_stage(ktn % STAGES, ktn);
        CP_COMMIT();
    }

    const int g  = lane >> 2;
    const int th = (lane & 3) * 2;
#pragma unroll
    for (int mi = 0; mi < 4; mi++) {
#pragma unroll
        for (int half = 0; half < 2; half++) {
            const int row = rowBase + wm0 + mi * 16 + g + half * 8;
#pragma unroll
            for (int ni = 0; ni < 4; ni++) {
                const int col = colBase + wn0 + ni * 8 + th;
                float v0 = c[mi][ni][half * 2 + 0];
                float v1 = c[mi][ni][half * 2 + 1];
                if (EPI == 1 || EPI == 3) {
                    const __half2 r16 = *(const __half2*)&res16[(size_t)row * N + col];
                    const float2 rf = __half22float2(r16);
                    v0 += bias[col]     + rf.x;
                    v1 += bias[col + 1] + rf.y;
                } else if (EPI == 2) {
                    v0 = gelu_exact(v0 + bias[col]);
                    v1 = gelu_exact(v1 + bias[col + 1]);
                } else if (EPI == 4) {
                    v0 *= sc; v1 *= sc;
                }
                if (EPI == 3)
                    *(float2*)&C32[(size_t)row * N + col] = make_float2(v0, v1);
                else
                    *(__half2*)&C16[(size_t)row * N + col] = __floats2half2_rn(v0, v1);
            }
        }
    }
}

template <int EPI>
__global__ __launch_bounds__(256) void tc_gemm(
    const __half* __restrict__ A, const __half* __restrict__ B,
    const float* __restrict__ bias, const __half* __restrict__ res16,
    float* __restrict__ C32, __half* __restrict__ C16,
    int M, int N, int K, float sc)
{
    extern __shared__ __half smh[];
    gemm_body<EPI>(smh, A, B, bias, res16, C32, C16, M, N, K, sc,
                   blockIdx.x, blockIdx.y);
}

// Fused Q + KV projection launch: blocks [0,1024) = KV, [1024,1280) = Q.
__global__ __launch_bounds__(256) void qkv_gemm(
    const __half* __restrict__ x16, const __half* __restrict__ c16,
    const __half* __restrict__ WqT, const __half* __restrict__ WkvT,
    __half* __restrict__ Q16, __half* __restrict__ KV16)
{
    extern __shared__ __half smh[];
    const int b = blockIdx.x;
    if (b < 1024) {
        gemm_body<4>(smh, c16, WkvT, nullptr, nullptr, nullptr, KV16,
                     MC, 2 * DIMM, DIMM, 1.0f, b & 15, b >> 4);
    } else {
        const int q = b - 1024;
        gemm_body<4>(smh, x16, WqT, nullptr, nullptr, nullptr, Q16,
                     MQ, DIMM, DIMM, 0.125f, q & 7, q >> 3);
    }
}

// ---------------------------------------------------------------------------
// MMA flash attention: 128 q-rows/CTA, cp.async K/V double-buffer,
// Q fragments hoisted to registers (loop-invariant).
// ---------------------------------------------------------------------------
#define PADA 72
#define QS_H   (128 * PADA)
#define KV_H   (64 * PADA)
#define ATT_SMEM ((QS_H + 4 * KV_H) * 2)

__global__ __launch_bounds__(256) void attn_mma(
    const __half* __restrict__ Q16, const __half* __restrict__ KV16,
    __half* __restrict__ O16)
{
    extern __shared__ __half sm[];
    const uint32_t qsB = smem_u32(sm);
    const uint32_t ksB = qsB + QS_H * 2;
    const uint32_t vsB = ksB + 2 * KV_H * 2;

    const int b = blockIdx.z;
    const int h = blockIdx.y;
    const int q0 = blockIdx.x * 128;
    const int tid = threadIdx.x;
    const int warp = tid >> 5;
    const int lane = tid & 31;
    const int g  = lane >> 2;
    const int th = (lane & 3) * 2;

    for (int i = tid; i < 1024; i += 256) {
        const int row = i >> 3, seg = (i & 7) * 8;
        *(uint4*)(sm + row * PADA + seg) =
            *(const uint4*)&Q16[(size_t)(b * LQ + q0 + row) * DIMM + h * DH + seg];
    }

    const int lrow = tid >> 3;
    const int lseg = (tid & 7) * 8;

    auto issue_kv = [&](int p, int k0) {
        const size_t gb = ((size_t)(b * LK + k0 + lrow)) * (2 * DIMM) + h * DH + lseg;
        const uint32_t kd = ksB + (uint32_t)(p * KV_H + lrow * PADA + lseg) * 2;
        const uint32_t vd = vsB + (uint32_t)(p * KV_H + lrow * PADA + lseg) * 2;
        CP_ASYNC16(kd, KV16 + gb);
        CP_ASYNC16(kd + 32 * PADA * 2, KV16 + gb + (size_t)32 * (2 * DIMM));
        CP_ASYNC16(vd, KV16 + gb + DIMM);
        CP_ASYNC16(vd + 32 * PADA * 2, KV16 + gb + DIMM + (size_t)32 * (2 * DIMM));
    };

    issue_kv(0, 0); CP_COMMIT();

    const int aRow = lane & 15;
    const int aCol = (lane >> 4) * 8;
    const int vq = lane >> 3;
    const int vi = lane & 7;
    const int vTokOff = (vq & 1) * 8 + vi;
    const int vDimOff = (vq >> 1) * 8;

    // Hoist Q fragments (loop-invariant) into registers
    __syncthreads();
    uint32_t aq[4][4];
#pragma unroll
    for (int kc = 0; kc < 4; kc++)
        ldsm_x4(aq[kc], qsB + (uint32_t)((warp * 16 + aRow) * PADA + kc * 16 + aCol) * 2);

    float m0 = -INFINITY, m1 = -INFINITY, l0 = 0.f, l1 = 0.f;
    float o[8][4];
#pragma unroll
    for (int j = 0; j < 8; j++)
#pragma unroll
        for (int q = 0; q < 4; q++) o[j][q] = 0.f;

    for (int kt = 0; kt < LK / 64; kt++) {
        const int p = kt & 1;
        CP_WAIT0();
        __syncthreads();
        if (kt + 1 < LK / 64) { issue_kv(p ^ 1, (kt + 1) * 64); CP_COMMIT(); }

        const uint32_t kBuf = ksB + (uint32_t)(p * KV_H) * 2;
        const uint32_t vBuf = vsB + (uint32_t)(p * KV_H) * 2;

        float s[8][4];
#pragma unroll
        for (int j = 0; j < 8; j++)
#pragma unroll
            for (int q = 0; q < 4; q++) s[j][q] = 0.f;

#pragma unroll
        for (int kc = 0; kc < 4; kc++) {
#pragma unroll
            for (int np = 0; np < 4; np++) {
                uint32_t bf[4];
                ldsm_x4(bf, kBuf + (uint32_t)((np * 16 + aRow) * PADA + kc * 16 + aCol) * 2);
                mma16816(s[np * 2],     aq[kc], bf[0], bf[2]);
                mma16816(s[np * 2 + 1], aq[kc], bf[1], bf[3]);
            }
        }

        float rm0 = s[0][0], rm1 = s[0][2];
#pragma unroll
        for (int j = 0; j < 8; j++) {
            rm0 = fmaxf(rm0, fmaxf(s[j][0], s[j][1]));
            rm1 = fmaxf(rm1, fmaxf(s[j][2], s[j][3]));
        }
        rm0 = fmaxf(rm0, __shfl_xor_sync(0xffffffffu, rm0, 1));
        rm0 = fmaxf(rm0, __shfl_xor_sync(0xffffffffu, rm0, 2));
        rm1 = fmaxf(rm1, __shfl_xor_sync(0xffffffffu, rm1, 1));
        rm1 = fmaxf(rm1, __shfl_xor_sync(0xffffffffu, rm1, 2));

        const float m0n = fmaxf(m0, rm0);
        const float m1n = fmaxf(m1, rm1);
        const float sc0 = __expf(m0 - m0n);
        const float sc1 = __expf(m1 - m1n);
        m0 = m0n; m1 = m1n;

        float ps0 = 0.f, ps1 = 0.f;
#pragma unroll
        for (int j = 0; j < 8; j++) {
            s[j][0] = __expf(s[j][0] - m0n);
            s[j][1] = __expf(s[j][1] - m0n);
            s[j][2] = __expf(s[j][2] - m1n);
            s[j][3] = __expf(s[j][3] - m1n);
            ps0 += s[j][0] + s[j][1];
            ps1 += s[j][2] + s[j][3];
        }
        l0 = l0 * sc0 + ps0;
        l1 = l1 * sc1 + ps1;
#pragma unroll
        for (int j = 0; j < 8; j++) {
            o[j][0] *= sc0; o[j][1] *= sc0;
            o[j][2] *= sc1; o[j][3] *= sc1;
        }

        uint32_t ap[4][4];
#pragma unroll
        for (int kc = 0; kc < 4; kc++) {
            __half2 h0 = __floats2half2_rn(s[2 * kc][0],     s[2 * kc][1]);
            __half2 h1 = __floats2half2_rn(s[2 * kc][2],     s[2 * kc][3]);
            __half2 h2 = __floats2half2_rn(s[2 * kc + 1][0], s[2 * kc + 1][1]);
            __half2 h3 = __floats2half2_rn(s[2 * kc + 1][2], s[2 * kc + 1][3]);
            ap[kc][0] = *(uint32_t*)&h0;
            ap[kc][1] = *(uint32_t*)&h1;
            ap[kc][2] = *(uint32_t*)&h2;
            ap[kc][3] = *(uint32_t*)&h3;
        }

#pragma unroll
        for (int kc = 0; kc < 4; kc++) {
#pragma unroll
            for (int nt2 = 0; nt2 < 4; nt2++) {
                uint32_t bv[4];
                const int token = kc * 16 + vTokOff;
                const int dim   = nt2 * 16 + vDimOff;
                ldsm_x4_t(bv, vBuf + (uint32_t)(token * PADA + dim) * 2);
                mma16816(o[nt2 * 2],     ap[kc], bv[0], bv[1]);
                mma16816(o[nt2 * 2 + 1], ap[kc], bv[2], bv[3]);
            }
        }
        __syncthreads();
    }

    l0 += __shfl_xor_sync(0xffffffffu, l0, 1);
    l0 += __shfl_xor_sync(0xffffffffu, l0, 2);
    l1 += __shfl_xor_sync(0xffffffffu, l1, 1);
    l1 += __shfl_xor_sync(0xffffffffu, l1, 2);
    const float inv0 = 1.0f / l0;
    const float inv1 = 1.0f / l1;

    const int row0 = b * LQ + q0 + warp * 16 + g;
#pragma unroll
    for (int j = 0; j < 8; j++) {
        const int col = h * DH + j * 8 + th;
        *(__half2*)&O16[(size_t)row0 * DIMM + col] =
            __floats2half2_rn(o[j][0] * inv0, o[j][1] * inv0);
        *(__half2*)&O16[(size_t)(row0 + 8) * DIMM + col] =
            __floats2half2_rn(o[j][2] * inv1, o[j][3] * inv1);
    }
}

// ---------------------------------------------------------------------------
// Launch sequence
// ---------------------------------------------------------------------------
extern "C" void kernel_launch(void* const* d_in, const int* in_sizes, int n_in,
                              void* d_out, int out_size)
{
    const float* x   = (const float*)d_in[0];
    const float* ctx = (const float*)d_in[1];
    const float* Wq  = (const float*)d_in[2];
    const float* Wk  = (const float*)d_in[3];
    const float* Wv  = (const float*)d_in[4];
    const float* Wo  = (const float*)d_in[5];
    const float* bo  = (const float*)d_in[6];
    const float* W1  = (const float*)d_in[7];
    const float* b1  = (const float*)d_in[8];
    const float* W2  = (const float*)d_in[9];
    const float* b2  = (const float*)d_in[10];
    float* out = (float*)d_out;

    __half *x16, *c16, *Q16, *KV16, *O16, *X116, *Hf16;
    __half *WqT, *WkvT, *WoT, *W1T, *W2T;
    cudaGetSymbolAddress((void**)&x16,  g_x16);
    cudaGetSymbolAddress((void**)&c16,  g_c16);
    cudaGetSymbolAddress((void**)&Q16,  g_Q16);
    cudaGetSymbolAddress((void**)&KV16, g_KV16);
    cudaGetSymbolAddress((void**)&O16,  g_O16);
    cudaGetSymbolAddress((void**)&X116, g_X116);
    cudaGetSymbolAddress((void**)&Hf16, g_Hf16);
    cudaGetSymbolAddress((void**)&WqT,  g_WqT);
    cudaGetSymbolAddress((void**)&WkvT, g_WkvT);
    cudaGetSymbolAddress((void**)&WoT,  g_WoT);
    cudaGetSymbolAddress((void**)&W1T,  g_W1T);
    cudaGetSymbolAddress((void**)&W2T,  g_W2T);

    cudaFuncSetAttribute(qkv_gemm,   cudaFuncAttributeMaxDynamicSharedMemorySize, GSMEM_BYTES);
    cudaFuncSetAttribute(tc_gemm<1>, cudaFuncAttributeMaxDynamicSharedMemorySize, GSMEM_BYTES);
    cudaFuncSetAttribute(tc_gemm<2>, cudaFuncAttributeMaxDynamicSharedMemorySize, GSMEM_BYTES);
    cudaFuncSetAttribute(tc_gemm<3>, cudaFuncAttributeMaxDynamicSharedMemorySize, GSMEM_BYTES);
    cudaFuncSetAttribute(attn_mma,   cudaFuncAttributeMaxDynamicSharedMemorySize, ATT_SMEM);

    // Preproc: conversions + all weight transposes in one launch
    preproc_all<<<15360, 256>>>(x, ctx, Wq, Wk, Wv, Wo, W1, W2,
                                x16, c16, WqT, WkvT, WoT, W1T, W2T);

    // Fused Q + KV projection (Q pre-scaled by 1/8)
    qkv_gemm<<<1280, 256, GSMEM_BYTES>>>(x16, c16, WqT, WkvT, Q16, KV16);

    // MMA flash attention -> O16
    attn_mma<<<dim3(LQ / 128, NH, BATCH), 256, ATT_SMEM>>>(Q16, KV16, O16);

    // X116 = fp16( O@Wo + bo + x16 )
    tc_gemm<1><<<dim3(DIMM / 128, MQ / 128), 256, GSMEM_BYTES>>>(O16, WoT, bo, x16, nullptr, X116, MQ, DIMM, DIMM, 1.0f);

    // Hf = gelu(X1@W1 + b1)
    tc_gemm<2><<<dim3(FF / 128, MQ / 128), 256, GSMEM_BYTES>>>(X116, W1T, b1, nullptr, nullptr, Hf16, MQ, FF, DIMM, 1.0f);

    // out = Hf@W2 + b2 + X116   (residual from fp16)
    tc_gemm<3><<<dim3(DIMM / 128, MQ / 128), 256, GSMEM_BYTES>>>(Hf16, W2T, b2, X116, out, nullptr, MQ, DIMM, FF, 1.0f);
}

// round 16
// speedup vs baseline: 1.0190x; 1.0042x over previous
#include <cuda_runtime.h>
#include <cuda_fp16.h>
#include <cstdint>
#include <math.h>

// ---------------------------------------------------------------------------
// Problem constants
// ---------------------------------------------------------------------------
#define BATCH 4
#define LQ 1024
#define LK 2048
#define DIMM 1024
#define NH 16
#define DH 64
#define FF 4096

#define MQ (BATCH * LQ)   // 4096 query rows
#define MC (BATCH * LK)   // 8192 context rows

// ---------------------------------------------------------------------------
// Scratch (__device__ globals; allocation-free rule)
// ---------------------------------------------------------------------------
__device__ __half g_x16 [MQ * DIMM];
__device__ __half g_c16 [MC * DIMM];
__device__ __half g_Q16 [MQ * DIMM];        // pre-scaled by 1/8
__device__ __half g_KV16[MC * 2 * DIMM];    // fused: row stride 2048, K | V
__device__ __half g_O16 [MQ * DIMM];
__device__ __half g_X116[MQ * DIMM];        // X1 in fp16 (sole copy)
__device__ __half g_Hf16[MQ * FF];

__device__ __half g_WqT [DIMM * DIMM];      // [N,K]
__device__ __half g_WkvT[2 * DIMM * DIMM];  // rows 0..1023 = Wk^T, 1024..2047 = Wv^T
__device__ __half g_WoT [DIMM * DIMM];
__device__ __half g_W1T [FF * DIMM];
__device__ __half g_W2T [DIMM * FF];

// ---------------------------------------------------------------------------
// Helpers
// ---------------------------------------------------------------------------
__device__ __forceinline__ uint32_t smem_u32(const void* p) {
    uint32_t a;
    asm("{ .reg .u64 t; cvta.to.shared.u64 t, %1; cvt.u32.u64 %0, t; }"
        : "=r"(a) : "l"(p));
    return a;
}

__device__ __forceinline__ void ldsm_x4(uint32_t* r, uint32_t addr) {
    asm volatile("ldmatrix.sync.aligned.m8n8.x4.shared.b16 {%0,%1,%2,%3}, [%4];"
                 : "=r"(r[0]), "=r"(r[1]), "=r"(r[2]), "=r"(r[3]) : "r"(addr));
}
__device__ __forceinline__ void ldsm_x4_t(uint32_t* r, uint32_t addr) {
    asm volatile("ldmatrix.sync.aligned.m8n8.x4.trans.shared.b16 {%0,%1,%2,%3}, [%4];"
                 : "=r"(r[0]), "=r"(r[1]), "=r"(r[2]), "=r"(r[3]) : "r"(addr));
}
__device__ __forceinline__ void ldsm_x2(uint32_t* r, uint32_t addr) {
    asm volatile("ldmatrix.sync.aligned.m8n8.x2.shared.b16 {%0,%1}, [%2];"
                 : "=r"(r[0]), "=r"(r[1]) : "r"(addr));
}

// D += A(16x16,row) * B(16x8,col), fp16 in, fp32 accum
__device__ __forceinline__ void mma16816(float* c, const uint32_t* a,
                                         uint32_t b0, uint32_t b1) {
    asm volatile(
        "mma.sync.aligned.m16n8k16.row.col.f32.f16.f16.f32 "
        "{%0,%1,%2,%3}, {%4,%5,%6,%7}, {%8,%9}, {%0,%1,%2,%3};"
        : "+f"(c[0]), "+f"(c[1]), "+f"(c[2]), "+f"(c[3])
        : "r"(a[0]), "r"(a[1]), "r"(a[2]), "r"(a[3]), "r"(b0), "r"(b1));
}

#define CP_ASYNC16(dst, src) \
    asm volatile("cp.async.cg.shared.global [%0], [%1], 16;" :: "r"(dst), "l"(src))
#define CP_COMMIT() asm volatile("cp.async.commit_group;" ::: "memory")
#define CP_WAIT1()  asm volatile("cp.async.wait_group 1;" ::: "memory")
#define CP_WAIT0()  asm volatile("cp.async.wait_group 0;" ::: "memory")

__device__ __forceinline__ float gelu_exact(float x) {
    return 0.5f * x * (1.0f + erff(x * 0.70710678118654752f));
}

// ---------------------------------------------------------------------------
// Preproc: cvt x16 / cvt c16 / all six weight transposes, in ONE launch
// ---------------------------------------------------------------------------
__device__ __forceinline__ void tr_tile(const float* __restrict__ W,
                                        __half* __restrict__ WT,
                                        int K, int N, int bx, int by,
                                        __half (*t)[68])
{
    const int n0 = bx * 64, k0 = by * 64;
    const int tid = threadIdx.x;
    const int lr = tid >> 4;
    const int lc = (tid & 15) * 4;
#pragma unroll
    for (int i = 0; i < 4; i++) {
        const int k = lr + i * 16;
        float4 v = *(const float4*)&W[(size_t)(k0 + k) * N + n0 + lc];
        __half2* dst = (__half2*)&t[k][lc];
        dst[0] = __floats2half2_rn(v.x, v.y);
        dst[1] = __floats2half2_rn(v.z, v.w);
    }
    __syncthreads();
    const int sn  = tid & 63;
    const int sk0 = (tid >> 6) * 16;
#pragma unroll
    for (int j2 = 0; j2 < 2; j2++) {
        __half buf[8];
#pragma unroll
        for (int j = 0; j < 8; j++) buf[j] = t[sk0 + j2 * 8 + j][sn];
        *(uint4*)&WT[(size_t)(n0 + sn) * K + k0 + sk0 + j2 * 8] = *(uint4*)buf;
    }
}

__device__ __forceinline__ void cvt_chunk(const float4* __restrict__ src,
                                          __half2* __restrict__ dst, int i)
{
    float4 v = src[i];
    dst[2 * i]     = __floats2half2_rn(v.x, v.y);
    dst[2 * i + 1] = __floats2half2_rn(v.z, v.w);
}

// blocks: [0,4096) cvt x | [4096,12288) cvt c | [12288,15360) transposes
__global__ __launch_bounds__(256) void preproc_all(
    const float* __restrict__ x,  const float* __restrict__ ctx,
    const float* __restrict__ Wq, const float* __restrict__ Wk,
    const float* __restrict__ Wv, const float* __restrict__ Wo,
    const float* __restrict__ W1, const float* __restrict__ W2,
    __half* __restrict__ x16,  __half* __restrict__ c16,
    __half* __restrict__ WqT,  __half* __restrict__ WkvT,
    __half* __restrict__ WoT,  __half* __restrict__ W1T, __half* __restrict__ W2T)
{
    __shared__ __half t[64][68];
    const int b = blockIdx.x;
    if (b < 4096) {
        cvt_chunk((const float4*)x, (__half2*)x16, b * 256 + threadIdx.x);
    } else if (b < 12288) {
        cvt_chunk((const float4*)ctx, (__half2*)c16, (b - 4096) * 256 + threadIdx.x);
    } else {
        const int tb = b - 12288;
        if (tb < 256)       tr_tile(Wq, WqT,                DIMM, DIMM, tb % 16,          tb / 16,          t);
        else if (tb < 512)  tr_tile(Wk, WkvT,               DIMM, DIMM, (tb - 256) % 16,  (tb - 256) / 16,  t);
        else if (tb < 768)  tr_tile(Wv, WkvT + DIMM * DIMM, DIMM, DIMM, (tb - 512) % 16,  (tb - 512) / 16,  t);
        else if (tb < 1024) tr_tile(Wo, WoT,                DIMM, DIMM, (tb - 768) % 16,  (tb - 768) / 16,  t);
        else if (tb < 2048) tr_tile(W1, W1T,                DIMM, FF,   (tb - 1024) % 64, (tb - 1024) / 64, t);
        else                tr_tile(W2, W2T,                FF,   DIMM, (tb - 2048) % 16, (tb - 2048) / 16, t);
    }
}

// ---------------------------------------------------------------------------
// HMMA fp16 GEMM body, selectable pipeline depth STG (2 or 3).
// C = A[M,K] @ B^T, B = WT[N,K]. CTA 128x128, BK=64, 256 threads.
// STG=3: many-wave launches (qkv, FFN1). STG=2: 2 CTAs/SM, single-wave
// for 256-CTA launches (Wo, FFN2).
// EPI: 1 bias + res16 -> fp16 out ; 2 gelu(acc+bias) -> fp16 ;
//      3 bias + res16 -> fp32 out ; 4 fp16 out, *sc
// ---------------------------------------------------------------------------
#define PADK 72
#define STAGE_HALVES (128 * PADK)
#define GSMEM(stg) ((stg) * 2 * STAGE_HALVES * 2)

template <int EPI, int STG>
__device__ __forceinline__ void gemm_body(
    __half* smh,
    const __half* __restrict__ A, const __half* __restrict__ B,
    const float* __restrict__ bias, const __half* __restrict__ res16,
    float* __restrict__ C32, __half* __restrict__ C16,
    int M, int N, int K, float sc, int bx, int by)
{
    const uint32_t asBase = smem_u32(smh);
    const uint32_t bsBase = asBase + STG * STAGE_HALVES * 2;

    const int tid  = threadIdx.x;
    const int warp = tid >> 5;
    const int lane = tid & 31;
    const int wm0 = (warp & 1) * 64;
    const int wn0 = (warp >> 1) * 32;

    const int rowBase = by * 128;
    const int colBase = bx * 128;
    const __half* Atile = A + (size_t)rowBase * K;
    const __half* Btile = B + (size_t)colBase * K;

    const int ldRow = tid >> 3;
    const int ldSeg = (tid & 7) * 8;

    const int aRow = (lane & 15);
    const int aCol = (lane >> 4) * 8;
    const int bRow = (lane & 7);
    const int bCol = ((lane >> 3) & 1) * 8;

    float c[4][4][4];
#pragma unroll
    for (int mi = 0; mi < 4; mi++)
#pragma unroll
        for (int ni = 0; ni < 4; ni++)
#pragma unroll
            for (int j = 0; j < 4; j++) c[mi][ni][j] = 0.0f;

    const int numK = K >> 6;

    auto issue_stage = [&](int stage, int kt) {
        const int k0 = kt * 64;
        const uint32_t ad = asBase + (uint32_t)((stage * 128 + ldRow) * PADK + ldSeg) * 2;
        const uint32_t bd = bsBase + (uint32_t)((stage * 128 + ldRow) * PADK + ldSeg) * 2;
        const __half* as = Atile + (size_t)ldRow * K + k0 + ldSeg;
        const __half* bs = Btile + (size_t)ldRow * K + k0 + ldSeg;
#pragma unroll
        for (int i = 0; i < 4; i++) {
            CP_ASYNC16(ad + (uint32_t)(i * 32 * PADK) * 2, as + (size_t)(i * 32) * K);
            CP_ASYNC16(bd + (uint32_t)(i * 32 * PADK) * 2, bs + (size_t)(i * 32) * K);
        }
    };

    auto compute_tile = [&](int st) {
        const uint32_t aBuf = asBase + (uint32_t)(st * STAGE_HALVES) * 2;
        const uint32_t bBuf = bsBase + (uint32_t)(st * STAGE_HALVES) * 2;
#pragma unroll
        for (int ks = 0; ks < 4; ks++) {
            uint32_t af[4][4], bf[4][2];
#pragma unroll
            for (int mi = 0; mi < 4; mi++)
                ldsm_x4(af[mi], aBuf + (uint32_t)((wm0 + mi * 16 + aRow) * PADK + ks * 16 + aCol) * 2);
#pragma unroll
            for (int ni = 0; ni < 4; ni++)
                ldsm_x2(bf[ni], bBuf + (uint32_t)((wn0 + ni * 8 + bRow) * PADK + ks * 16 + bCol) * 2);
#pragma unroll
            for (int mi = 0; mi < 4; mi++)
#pragma unroll
                for (int ni = 0; ni < 4; ni++)
                    mma16816(c[mi][ni], af[mi], bf[ni][0], bf[ni][1]);
        }
    };

    if (STG == 3) {
        issue_stage(0, 0); CP_COMMIT();
        issue_stage(1, 1); CP_COMMIT();
        for (int kt = 0; kt < numK; kt++) {
            CP_WAIT1();
            __syncthreads();
            compute_tile(kt % 3);
            const int ktn = kt + 2;
            if (ktn < numK) issue_stage(ktn % 3, ktn);
            CP_COMMIT();
        }
    } else {
        issue_stage(0, 0); CP_COMMIT();
        for (int kt = 0; kt < numK; kt++) {
            const int p = kt & 1;
            CP_WAIT0();
            __syncthreads();
            if (kt + 1 < numK) { issue_stage(p ^ 1, kt + 1); CP_COMMIT(); }
            compute_tile(p);
        }
    }

    const int g  = lane >> 2;
    const int th = (lane & 3) * 2;
#pragma unroll
    for (int mi = 0; mi < 4; mi++) {
#pragma unroll
        for (int half = 0; half < 2; half++) {
            const int row = rowBase + wm0 + mi * 16 + g + half * 8;
#pragma unroll
            for (int ni = 0; ni < 4; ni++) {
                const int col = colBase + wn0 + ni * 8 + th;
                float v0 = c[mi][ni][half * 2 + 0];
                float v1 = c[mi][ni][half * 2 + 1];
                if (EPI == 1 || EPI == 3) {
                    const __half2 r16 = *(const __half2*)&res16[(size_t)row * N + col];
                    const float2 rf = __half22float2(r16);
                    v0 += bias[col]     + rf.x;
                    v1 += bias[col + 1] + rf.y;
                } else if (EPI == 2) {
                    v0 = gelu_exact(v0 + bias[col]);
                    v1 = gelu_exact(v1 + bias[col + 1]);
                } else if (EPI == 4) {
                    v0 *= sc; v1 *= sc;
                }
                if (EPI == 3)
                    *(float2*)&C32[(size_t)row * N + col] = make_float2(v0, v1);
                else
                    *(__half2*)&C16[(size_t)row * N + col] = __floats2half2_rn(v0, v1);
            }
        }
    }
}

template <int EPI, int STG>
__global__ __launch_bounds__(256) void tc_gemm(
    const __half* __restrict__ A, const __half* __restrict__ B,
    const float* __restrict__ bias, const __half* __restrict__ res16,
    float* __restrict__ C32, __half* __restrict__ C16,
    int M, int N, int K, float sc)
{
    extern __shared__ __half smh[];
    gemm_body<EPI, STG>(smh, A, B, bias, res16, C32, C16, M, N, K, sc,
                        blockIdx.x, blockIdx.y);
}

// Fused Q + KV projection launch (3-stage): [0,1024) = KV, [1024,1280) = Q.
__global__ __launch_bounds__(256) void qkv_gemm(
    const __half* __restrict__ x16, const __half* __restrict__ c16,
    const __half* __restrict__ WqT, const __half* __restrict__ WkvT,
    __half* __restrict__ Q16, __half* __restrict__ KV16)
{
    extern __shared__ __half smh[];
    const int b = blockIdx.x;
    if (b < 1024) {
        gemm_body<4, 3>(smh, c16, WkvT, nullptr, nullptr, nullptr, KV16,
                        MC, 2 * DIMM, DIMM, 1.0f, b & 15, b >> 4);
    } else {
        const int q = b - 1024;
        gemm_body<4, 3>(smh, x16, WqT, nullptr, nullptr, nullptr, Q16,
                        MQ, DIMM, DIMM, 0.125f, q & 7, q >> 3);
    }
}

// ---------------------------------------------------------------------------
// MMA flash attention: 128 q-rows/CTA, cp.async K/V double-buffer,
// Q fragments hoisted to registers (loop-invariant).
// ---------------------------------------------------------------------------
#define PADA 72
#define QS_H   (128 * PADA)
#define KV_H   (64 * PADA)
#define ATT_SMEM ((QS_H + 4 * KV_H) * 2)

__global__ __launch_bounds__(256) void attn_mma(
    const __half* __restrict__ Q16, const __half* __restrict__ KV16,
    __half* __restrict__ O16)
{
    extern __shared__ __half sm[];
    const uint32_t qsB = smem_u32(sm);
    const uint32_t ksB = qsB + QS_H * 2;
    const uint32_t vsB = ksB + 2 * KV_H * 2;

    const int b = blockIdx.z;
    const int h = blockIdx.y;
    const int q0 = blockIdx.x * 128;
    const int tid = threadIdx.x;
    const int warp = tid >> 5;
    const int lane = tid & 31;
    const int g  = lane >> 2;
    const int th = (lane & 3) * 2;

    for (int i = tid; i < 1024; i += 256) {
        const int row = i >> 3, seg = (i & 7) * 8;
        *(uint4*)(sm + row * PADA + seg) =
            *(const uint4*)&Q16[(size_t)(b * LQ + q0 + row) * DIMM + h * DH + seg];
    }

    const int lrow = tid >> 3;
    const int lseg = (tid & 7) * 8;

    auto issue_kv = [&](int p, int k0) {
        const size_t gb = ((size_t)(b * LK + k0 + lrow)) * (2 * DIMM) + h * DH + lseg;
        const uint32_t kd = ksB + (uint32_t)(p * KV_H + lrow * PADA + lseg) * 2;
        const uint32_t vd = vsB + (uint32_t)(p * KV_H + lrow * PADA + lseg) * 2;
        CP_ASYNC16(kd, KV16 + gb);
        CP_ASYNC16(kd + 32 * PADA * 2, KV16 + gb + (size_t)32 * (2 * DIMM));
        CP_ASYNC16(vd, KV16 + gb + DIMM);
        CP_ASYNC16(vd + 32 * PADA * 2, KV16 + gb + DIMM + (size_t)32 * (2 * DIMM));
    };

    issue_kv(0, 0); CP_COMMIT();

    const int aRow = lane & 15;
    const int aCol = (lane >> 4) * 8;
    const int vq = lane >> 3;
    const int vi = lane & 7;
    const int vTokOff = (vq & 1) * 8 + vi;
    const int vDimOff = (vq >> 1) * 8;

    // Hoist Q fragments (loop-invariant) into registers
    __syncthreads();
    uint32_t aq[4][4];
#pragma unroll
    for (int kc = 0; kc < 4; kc++)
        ldsm_x4(aq[kc], qsB + (uint32_t)((warp * 16 + aRow) * PADA + kc * 16 + aCol) * 2);

    float m0 = -INFINITY, m1 = -INFINITY, l0 = 0.f, l1 = 0.f;
    float o[8][4];
#pragma unroll
    for (int j = 0; j < 8; j++)
#pragma unroll
        for (int q = 0; q < 4; q++) o[j][q] = 0.f;

    for (int kt = 0; kt < LK / 64; kt++) {
        const int p = kt & 1;
        CP_WAIT0();
        __syncthreads();
        if (kt + 1 < LK / 64) { issue_kv(p ^ 1, (kt + 1) * 64); CP_COMMIT(); }

        const uint32_t kBuf = ksB + (uint32_t)(p * KV_H) * 2;
        const uint32_t vBuf = vsB + (uint32_t)(p * KV_H) * 2;

        float s[8][4];
#pragma unroll
        for (int j = 0; j < 8; j++)
#pragma unroll
            for (int q = 0; q < 4; q++) s[j][q] = 0.f;

#pragma unroll
        for (int kc = 0; kc < 4; kc++) {
#pragma unroll
            for (int np = 0; np < 4; np++) {
                uint32_t bf[4];
                ldsm_x4(bf, kBuf + (uint32_t)((np * 16 + aRow) * PADA + kc * 16 + aCol) * 2);
                mma16816(s[np * 2],     aq[kc], bf[0], bf[2]);
                mma16816(s[np * 2 + 1], aq[kc], bf[1], bf[3]);
            }
        }

        float rm0 = s[0][0], rm1 = s[0][2];
#pragma unroll
        for (int j = 0; j < 8; j++) {
            rm0 = fmaxf(rm0, fmaxf(s[j][0], s[j][1]));
            rm1 = fmaxf(rm1, fmaxf(s[j][2], s[j][3]));
        }
        rm0 = fmaxf(rm0, __shfl_xor_sync(0xffffffffu, rm0, 1));
        rm0 = fmaxf(rm0, __shfl_xor_sync(0xffffffffu, rm0, 2));
        rm1 = fmaxf(rm1, __shfl_xor_sync(0xffffffffu, rm1, 1));
        rm1 = fmaxf(rm1, __shfl_xor_sync(0xffffffffu, rm1, 2));

        const float m0n = fmaxf(m0, rm0);
        const float m1n = fmaxf(m1, rm1);
        const float sc0 = __expf(m0 - m0n);
        const float sc1 = __expf(m1 - m1n);
        m0 = m0n; m1 = m1n;

        float ps0 = 0.f, ps1 = 0.f;
#pragma unroll
        for (int j = 0; j < 8; j++) {
            s[j][0] = __expf(s[j][0] - m0n);
            s[j][1] = __expf(s[j][1] - m0n);
            s[j][2] = __expf(s[j][2] - m1n);
            s[j][3] = __expf(s[j][3] - m1n);
            ps0 += s[j][0] + s[j][1];
            ps1 += s[j][2] + s[j][3];
        }
        l0 = l0 * sc0 + ps0;
        l1 = l1 * sc1 + ps1;
#pragma unroll
        for (int j = 0; j < 8; j++) {
            o[j][0] *= sc0; o[j][1] *= sc0;
            o[j][2] *= sc1; o[j][3] *= sc1;
        }

        uint32_t ap[4][4];
#pragma unroll
        for (int kc = 0; kc < 4; kc++) {
            __half2 h0 = __floats2half2_rn(s[2 * kc][0],     s[2 * kc][1]);
            __half2 h1 = __floats2half2_rn(s[2 * kc][2],     s[2 * kc][3]);
            __half2 h2 = __floats2half2_rn(s[2 * kc + 1][0], s[2 * kc + 1][1]);
            __half2 h3 = __floats2half2_rn(s[2 * kc + 1][2], s[2 * kc + 1][3]);
            ap[kc][0] = *(uint32_t*)&h0;
            ap[kc][1] = *(uint32_t*)&h1;
            ap[kc][2] = *(uint32_t*)&h2;
            ap[kc][3] = *(uint32_t*)&h3;
        }

#pragma unroll
        for (int kc = 0; kc < 4; kc++) {
#pragma unroll
            for (int nt2 = 0; nt2 < 4; nt2++) {
                uint32_t bv[4];
                const int token = kc * 16 + vTokOff;
                const int dim   = nt2 * 16 + vDimOff;
                ldsm_x4_t(bv, vBuf + (uint32_t)(token * PADA + dim) * 2);
                mma16816(o[nt2 * 2],     ap[kc], bv[0], bv[1]);
                mma16816(o[nt2 * 2 + 1], ap[kc], bv[2], bv[3]);
            }
        }
        __syncthreads();
    }

    l0 += __shfl_xor_sync(0xffffffffu, l0, 1);
    l0 += __shfl_xor_sync(0xffffffffu, l0, 2);
    l1 += __shfl_xor_sync(0xffffffffu, l1, 1);
    l1 += __shfl_xor_sync(0xffffffffu, l1, 2);
    const float inv0 = 1.0f / l0;
    const float inv1 = 1.0f / l1;

    const int row0 = b * LQ + q0 + warp * 16 + g;
#pragma unroll
    for (int j = 0; j < 8; j++) {
        const int col = h * DH + j * 8 + th;
        *(__half2*)&O16[(size_t)row0 * DIMM + col] =
            __floats2half2_rn(o[j][0] * inv0, o[j][1] * inv0);
        *(__half2*)&O16[(size_t)(row0 + 8) * DIMM + col] =
            __floats2half2_rn(o[j][2] * inv1, o[j][3] * inv1);
    }
}

// ---------------------------------------------------------------------------
// Launch sequence
// ---------------------------------------------------------------------------
extern "C" void kernel_launch(void* const* d_in, const int* in_sizes, int n_in,
                              void* d_out, int out_size)
{
    const float* x   = (const float*)d_in[0];
    const float* ctx = (const float*)d_in[1];
    const float* Wq  = (const float*)d_in[2];
    const float* Wk  = (const float*)d_in[3];
    const float* Wv  = (const float*)d_in[4];
    const float* Wo  = (const float*)d_in[5];
    const float* bo  = (const float*)d_in[6];
    const float* W1  = (const float*)d_in[7];
    const float* b1  = (const float*)d_in[8];
    const float* W2  = (const float*)d_in[9];
    const float* b2  = (const float*)d_in[10];
    float* out = (float*)d_out;

    __half *x16, *c16, *Q16, *KV16, *O16, *X116, *Hf16;
    __half *WqT, *WkvT, *WoT, *W1T, *W2T;
    cudaGetSymbolAddress((void**)&x16,  g_x16);
    cudaGetSymbolAddress((void**)&c16,  g_c16);
    cudaGetSymbolAddress((void**)&Q16,  g_Q16);
    cudaGetSymbolAddress((void**)&KV16, g_KV16);
    cudaGetSymbolAddress((void**)&O16,  g_O16);
    cudaGetSymbolAddress((void**)&X116, g_X116);
    cudaGetSymbolAddress((void**)&Hf16, g_Hf16);
    cudaGetSymbolAddress((void**)&WqT,  g_WqT);
    cudaGetSymbolAddress((void**)&WkvT, g_WkvT);
    cudaGetSymbolAddress((void**)&WoT,  g_WoT);
    cudaGetSymbolAddress((void**)&W1T,  g_W1T);
    cudaGetSymbolAddress((void**)&W2T,  g_W2T);

    cudaFuncSetAttribute(qkv_gemm,        cudaFuncAttributeMaxDynamicSharedMemorySize, GSMEM(3));
    cudaFuncSetAttribute((tc_gemm<1, 2>), cudaFuncAttributeMaxDynamicSharedMemorySize, GSMEM(2));
    cudaFuncSetAttribute((tc_gemm<2, 3>), cudaFuncAttributeMaxDynamicSharedMemorySize, GSMEM(3));
    cudaFuncSetAttribute((tc_gemm<3, 2>), cudaFuncAttributeMaxDynamicSharedMemorySize, GSMEM(2));
    cudaFuncSetAttribute(attn_mma,        cudaFuncAttributeMaxDynamicSharedMemorySize, ATT_SMEM);

    // Preproc: conversions + all weight transposes in one launch
    preproc_all<<<15360, 256>>>(x, ctx, Wq, Wk, Wv, Wo, W1, W2,
                                x16, c16, WqT, WkvT, WoT, W1T, W2T);

    // Fused Q + KV projection (3-stage; Q pre-scaled by 1/8)
    qkv_gemm<<<1280, 256, GSMEM(3)>>>(x16, c16, WqT, WkvT, Q16, KV16);

    // MMA flash attention -> O16
    attn_mma<<<dim3(LQ / 128, NH, BATCH), 256, ATT_SMEM>>>(Q16, KV16, O16);

    // X116 = fp16( O@Wo + bo + x16 )   (2-stage: 256 CTAs -> single wave)
    tc_gemm<1, 2><<<dim3(DIMM / 128, MQ / 128), 256, GSMEM(2)>>>(O16, WoT, bo, x16, nullptr, X116, MQ, DIMM, DIMM, 1.0f);

    // Hf = gelu(X1@W1 + b1)   (3-stage: 1024 CTAs)
    tc_gemm<2, 3><<<dim3(FF / 128, MQ / 128), 256, GSMEM(3)>>>(X116, W1T, b1, nullptr, nullptr, Hf16, MQ, FF, DIMM, 1.0f);

    // out = Hf@W2 + b2 + X116   (2-stage: 256 CTAs -> single wave)
    tc_gemm<3, 2><<<dim3(DIMM / 128, MQ / 128), 256, GSMEM(2)>>>(Hf16, W2T, b2, X116, out, nullptr, MQ, DIMM, FF, 1.0f);
}